// round 2
// baseline (speedup 1.0000x reference)
#include <cuda_runtime.h>

#define SQ   1024
#define BS   64
#define HD   512
#define ED   256
#define VB   32000
#define G3   1536
#define EOSV 2
#define NEOS 32

#define NBG  4            // batch groups (16 rows each)
#define NRG  32           // j groups (16 h-dims each)
#define NCTA (NBG*NRG)    // 128 persistent CTAs

typedef unsigned long long u64;

// ------------------- device scratch (static only; no allocs) ----------------
__device__ float    g_Gtab[(size_t)VB * G3];   // ~197MB input-projection table
__device__ float    g_h[2][BS * HD];           // double-buffered hidden state
__device__ int      g_dest[SQ * BS];           // EOS compaction slot or -1
__device__ unsigned g_ctr[NBG * 32];           // per-batch-group barrier counters

// ------------------- packed f32x2 helpers ----------------------------------
__device__ __forceinline__ u64 ffma2(u64 a, u64 b, u64 c) {
    u64 d;
    asm("fma.rn.f32x2 %0, %1, %2, %3;" : "=l"(d) : "l"(a), "l"(b), "l"(c));
    return d;
}
__device__ __forceinline__ u64 bcast2(float x) {
    u64 d;
    asm("mov.b64 %0, {%1, %1};" : "=l"(d) : "f"(x));
    return d;
}
__device__ __forceinline__ float2 unpack2(u64 v) {
    float2 f;
    asm("mov.b64 {%0, %1}, %2;" : "=f"(f.x), "=f"(f.y) : "l"(v));
    return f;
}
__device__ __forceinline__ float hsum2(u64 v) {
    float2 f = unpack2(v);
    return f.x + f.y;
}
__device__ __forceinline__ unsigned ld_acq(const unsigned* p) {
    unsigned v;
    asm volatile("ld.acquire.gpu.global.u32 %0, [%1];" : "=r"(v) : "l"(p));
    return v;
}

// ------------------- prep: h0=0, counters=0, EOS destination scan ----------
__global__ void prep_kernel(const int* __restrict__ tokens) {
    int b = blockIdx.x;        // 64 blocks, one batch column each
    int t = threadIdx.x;       // 32 threads
    if (b == 0 && t < NBG) g_ctr[t * 32] = 0u;
    for (int i = t; i < HD; i += 32) g_h[0][b * HD + i] = 0.f;

    // each thread scans 32 tokens; warp prefix-scan of EOS counts
    int s0 = t * 32;
    int cnt = 0;
    #pragma unroll
    for (int i = 0; i < 32; i++) cnt += (tokens[b * SQ + s0 + i] == EOSV);
    int pre = cnt;
    #pragma unroll
    for (int m = 1; m < 32; m <<= 1) {
        int v = __shfl_up_sync(0xffffffffu, pre, m);
        if (t >= m) pre += v;
    }
    pre -= cnt;                // exclusive prefix
    int k = pre;
    #pragma unroll
    for (int i = 0; i < 32; i++) {
        int s = s0 + i;
        bool e = (tokens[b * SQ + s] == EOSV);
        g_dest[s * BS + b] = (e && k < NEOS) ? k : -1;
        k += e;
    }
}

// ------------------- Gtab GEMM: G[t][g] = sum_k emb[t][k]*w_ih[g][k]+b_ih[g]
// M=32000 x N=1536 x K=256.  128x128 tile, 16-k steps, 8x8 microtile, f32x2.
__global__ void __launch_bounds__(256) gtab_kernel(
    const float* __restrict__ emb,
    const float* __restrict__ w_ih,
    const float* __restrict__ b_ih)
{
    __shared__ float A_sT[16 * 132];   // [k][t_local]  (transposed, padded)
    __shared__ float B_sT[16 * 132];   // [k][g_local]

    int tid = threadIdx.x;
    int tx = tid & 15, ty = tid >> 4;
    int g0 = blockIdx.x * 128;         // 12 tiles
    int t0 = blockIdx.y * 128;         // 250 tiles

    u64 acc[8][4];
    #pragma unroll
    for (int i = 0; i < 8; i++)
        #pragma unroll
        for (int j = 0; j < 4; j++) acc[i][j] = 0ull;

    for (int k0 = 0; k0 < ED; k0 += 16) {
        __syncthreads();
        #pragma unroll
        for (int i = 0; i < 2; i++) {
            int ff  = tid + i * 256;       // 0..511 float4 slots
            int row = ff >> 2;             // 0..127
            int c4  = (ff & 3) * 4;        // 0,4,8,12
            float4 va = *(const float4*)&emb[(size_t)(t0 + row) * ED + k0 + c4];
            A_sT[(c4 + 0) * 132 + row] = va.x;
            A_sT[(c4 + 1) * 132 + row] = va.y;
            A_sT[(c4 + 2) * 132 + row] = va.z;
            A_sT[(c4 + 3) * 132 + row] = va.w;
            float4 vb = *(const float4*)&w_ih[(size_t)(g0 + row) * ED + k0 + c4];
            B_sT[(c4 + 0) * 132 + row] = vb.x;
            B_sT[(c4 + 1) * 132 + row] = vb.y;
            B_sT[(c4 + 2) * 132 + row] = vb.z;
            B_sT[(c4 + 3) * 132 + row] = vb.w;
        }
        __syncthreads();
        #pragma unroll
        for (int k = 0; k < 16; k++) {
            float4 a0 = *(const float4*)&A_sT[k * 132 + ty * 4];
            float4 a1 = *(const float4*)&A_sT[k * 132 + 64 + ty * 4];
            u64 b0x = *(const u64*)&B_sT[k * 132 + tx * 4];
            u64 b0y = *(const u64*)&B_sT[k * 132 + tx * 4 + 2];
            u64 b1x = *(const u64*)&B_sT[k * 132 + 64 + tx * 4];
            u64 b1y = *(const u64*)&B_sT[k * 132 + 64 + tx * 4 + 2];
            float af[8] = {a0.x, a0.y, a0.z, a0.w, a1.x, a1.y, a1.z, a1.w};
            #pragma unroll
            for (int i = 0; i < 8; i++) {
                u64 ap = bcast2(af[i]);
                acc[i][0] = ffma2(ap, b0x, acc[i][0]);
                acc[i][1] = ffma2(ap, b0y, acc[i][1]);
                acc[i][2] = ffma2(ap, b1x, acc[i][2]);
                acc[i][3] = ffma2(ap, b1y, acc[i][3]);
            }
        }
    }

    float4 bia0 = *(const float4*)&b_ih[g0 + tx * 4];
    float4 bia1 = *(const float4*)&b_ih[g0 + 64 + tx * 4];
    #pragma unroll
    for (int i = 0; i < 8; i++) {
        int trow = t0 + (i >> 2) * 64 + ty * 4 + (i & 3);
        float2 c0 = unpack2(acc[i][0]);
        float2 c1 = unpack2(acc[i][1]);
        float2 c2 = unpack2(acc[i][2]);
        float2 c3 = unpack2(acc[i][3]);
        float4 o0 = make_float4(c0.x + bia0.x, c0.y + bia0.y, c1.x + bia0.z, c1.y + bia0.w);
        float4 o1 = make_float4(c2.x + bia1.x, c2.y + bia1.y, c3.x + bia1.z, c3.y + bia1.w);
        *(float4*)&g_Gtab[(size_t)trow * G3 + g0 + tx * 4]      = o0;
        *(float4*)&g_Gtab[(size_t)trow * G3 + g0 + 64 + tx * 4] = o1;
    }
}

// ------------------- persistent GRU recurrence ------------------------------
// CTA(bg,rg): 16 batches x 16 h-dims. Thread(jl=tid>>4, ks=tid&15) holds
// W_hh[g][jG][ks*32 .. +32) in registers (rotated order, bank-conflict free),
// computes split-K partials, reduces via shfl.bfly within 16-lane groups.
__global__ void __launch_bounds__(256, 1) gru_kernel(
    const int*   __restrict__ tokens,
    const float* __restrict__ w_hh,
    const float* __restrict__ b_hh,
    float*       __restrict__ out)
{
    __shared__ float h_s[16][HD];           // 32KB: this bg's h slice
    __shared__ float gi_s[16][16][3];       // input projections for this step
    __shared__ int   dest_s[16];

    int tid = threadIdx.x;
    int jl = tid >> 4, ks = tid & 15;
    int bg = blockIdx.x & 3, rg = blockIdx.x >> 2;
    int jG = rg * 16 + jl;

    // one-time W_hh register load, rotated k order (matches swizzled reads)
    u64 wr[16], wz[16], wn[16];
    #pragma unroll
    for (int i = 0; i < 16; i++) {
        int col = ks * 32 + ((2 * i + 2 * ks) & 31);
        wr[i] = *(const u64*)&w_hh[(size_t)(0 * HD + jG) * HD + col];
        wz[i] = *(const u64*)&w_hh[(size_t)(1 * HD + jG) * HD + col];
        wn[i] = *(const u64*)&w_hh[(size_t)(2 * HD + jG) * HD + col];
    }
    float bhr = b_hh[jG], bhz = b_hh[HD + jG], bhn = b_hh[2 * HD + jG];

    // prefetch role: this thread fetches gi for (batch pb, h-dim jpf)
    int pb  = tid >> 4;
    int jpf = tid & 15;
    int bG_pf = bg * 16 + pb;

    for (int s = 0; s < SQ; s++) {
        // --- gi prefetch (independent of h; overlaps DRAM latency) ---
        int tok = tokens[bG_pf * SQ + s];
        const float* gp = &g_Gtab[(size_t)tok * G3 + rg * 16 + jpf];
        float p0 = __ldcs(gp);
        float p1 = __ldcs(gp + HD);
        float p2 = __ldcs(gp + 2 * HD);

        // --- cooperative h load (L1-bypass: produced by other SMs) ---
        const float* hsrc = &g_h[s & 1][bg * 16 * HD];
        float4 hv4[8];
        #pragma unroll
        for (int i = 0; i < 8; i++) {
            int f = tid + i * 256;
            hv4[i] = __ldcg((const float4*)&hsrc[(f >> 7) * HD + (f & 127) * 4]);
        }
        #pragma unroll
        for (int i = 0; i < 8; i++) {
            int f = tid + i * 256;
            *(float4*)&h_s[f >> 7][(f & 127) * 4] = hv4[i];
        }
        gi_s[pb][jpf][0] = p0;
        gi_s[pb][jpf][1] = p1;
        gi_s[pb][jpf][2] = p2;
        if (jpf == 0) dest_s[pb] = g_dest[s * BS + bG_pf];
        __syncthreads();

        #pragma unroll 1
        for (int b = 0; b < 16; b++) {
            u64 aR = 0ull, aZ = 0ull, aN = 0ull;
            const float* hb = h_s[b];
            #pragma unroll
            for (int i = 0; i < 16; i++) {
                int col = ks * 32 + ((2 * i + 2 * ks) & 31);   // rotated: 16 distinct banks
                u64 hv = *(const u64*)&hb[col];
                aR = ffma2(wr[i], hv, aR);
                aZ = ffma2(wz[i], hv, aZ);
                aN = ffma2(wn[i], hv, aN);
            }
            float r_s = hsum2(aR), z_s = hsum2(aZ), n_s = hsum2(aN);
            #pragma unroll
            for (int m = 1; m < 16; m <<= 1) {
                r_s += __shfl_xor_sync(0xffffffffu, r_s, m);
                z_s += __shfl_xor_sync(0xffffffffu, z_s, m);
                n_s += __shfl_xor_sync(0xffffffffu, n_s, m);
            }
            float gir = gi_s[b][jl][0], giz = gi_s[b][jl][1], gin = gi_s[b][jl][2];
            float hprev = h_s[b][jG];
            float r  = 1.f / (1.f + __expf(-(gir + r_s + bhr)));
            float z  = 1.f / (1.f + __expf(-(giz + z_s + bhz)));
            float nn = gin + r * (n_s + bhn);
            float t2 = __expf(-2.f * nn);
            float n  = 2.f / (1.f + t2) - 1.f;             // tanh, inf-safe
            float hnew = fmaf(z, hprev - n, n);            // (1-z)n + z*h
            if (ks == 0) {
                g_h[(s + 1) & 1][(bg * 16 + b) * HD + jG] = hnew;
                int d = dest_s[b];
                if (d >= 0) out[((size_t)d * BS + bg * 16 + b) * HD + jG] = hnew;
            }
        }

        // --- per-batch-group barrier (32 CTAs) ---
        __syncthreads();
        if (tid == 0) {
            __threadfence();
            atomicAdd(&g_ctr[bg * 32], 1u);
            unsigned tgt = 32u * (unsigned)(s + 1);
            while (ld_acq(&g_ctr[bg * 32]) < tgt) { }
        }
        __syncthreads();
    }
}

// ------------------- launch -------------------------------------------------
extern "C" void kernel_launch(void* const* d_in, const int* in_sizes, int n_in,
                              void* d_out, int out_size) {
    const int*   tokens = (const int*)d_in[0];
    const float* emb    = (const float*)d_in[1];
    const float* w_ih   = (const float*)d_in[2];
    const float* w_hh   = (const float*)d_in[3];
    const float* b_ih   = (const float*)d_in[4];
    const float* b_hh   = (const float*)d_in[5];
    float* out = (float*)d_out;

    prep_kernel<<<BS, 32>>>(tokens);
    gtab_kernel<<<dim3(G3 / 128, VB / 128), 256>>>(emb, w_ih, b_ih);
    gru_kernel<<<NCTA, 256>>>(tokens, w_hh, b_hh, out);
}

// round 3
// speedup vs baseline: 1.7509x; 1.7509x over previous
#include <cuda_runtime.h>

#define SQ   1024
#define BS   64
#define HD   512
#define ED   256
#define VB   32000
#define G3   1536
#define EOSV 2
#define NEOS 32

#define NBG  4            // batch groups (16 rows each)
#define NRG  32           // j groups (16 h-dims each)
#define NCTA (NBG*NRG)    // 128 persistent CTAs

typedef unsigned long long u64;

// ------------------- device scratch (static only; no allocs) ----------------
__device__ float    g_Gtab[(size_t)VB * G3];   // ~197MB input-projection table
__device__ float    g_h[2][BS * HD];           // double-buffered hidden state
__device__ int      g_dest[SQ * BS];           // EOS compaction slot or -1
__device__ unsigned g_ctr[NBG * 32];           // per-batch-group barrier counters

// ------------------- packed f32x2 helpers ----------------------------------
__device__ __forceinline__ u64 ffma2(u64 a, u64 b, u64 c) {
    u64 d;
    asm("fma.rn.f32x2 %0, %1, %2, %3;" : "=l"(d) : "l"(a), "l"(b), "l"(c));
    return d;
}
__device__ __forceinline__ float2 unpack2(u64 v) {
    float2 f;
    asm("mov.b64 {%0, %1}, %2;" : "=f"(f.x), "=f"(f.y) : "l"(v));
    return f;
}
__device__ __forceinline__ float hsum2(u64 v) {
    float2 f = unpack2(v);
    return f.x + f.y;
}
__device__ __forceinline__ u64 bcast2(float x) {
    u64 d;
    asm("mov.b64 %0, {%1, %1};" : "=l"(d) : "f"(x));
    return d;
}
__device__ __forceinline__ unsigned ld_acq(const unsigned* p) {
    unsigned v;
    asm volatile("ld.acquire.gpu.global.u32 %0, [%1];" : "=r"(v) : "l"(p));
    return v;
}

// ------------------- Gtab GEMM (+fused prep): G = w_ih * emb^T + b_ih ------
// M=32000 x N=1536 x K=256.  128x128 tile, 16-k steps, 8x8 microtile, f32x2.
// First 64 flat CTAs additionally run the prep work (h0=0, counters, EOS scan)
// on their warp 0; gtab fully completes before gru launches (stream order).
__global__ void __launch_bounds__(256) gtab_kernel(
    const float* __restrict__ emb,
    const float* __restrict__ w_ih,
    const float* __restrict__ b_ih,
    const int*   __restrict__ tokens)
{
    // ---- fused prep ----
    int fid = blockIdx.y * 12 + blockIdx.x;
    if (fid < BS && threadIdx.x < 32) {
        int b = fid, t = threadIdx.x;
        if (fid == 0 && t < NBG) g_ctr[t * 32] = 0u;
        for (int i = t; i < HD; i += 32) g_h[0][b * HD + i] = 0.f;
        int s0 = t * 32;
        int cnt = 0;
        #pragma unroll
        for (int i = 0; i < 32; i++) cnt += (tokens[b * SQ + s0 + i] == EOSV);
        int pre = cnt;
        #pragma unroll
        for (int m = 1; m < 32; m <<= 1) {
            int v = __shfl_up_sync(0xffffffffu, pre, m);
            if (t >= m) pre += v;
        }
        pre -= cnt;
        int k = pre;
        #pragma unroll
        for (int i = 0; i < 32; i++) {
            int s = s0 + i;
            bool e = (tokens[b * SQ + s] == EOSV);
            g_dest[s * BS + b] = (e && k < NEOS) ? k : -1;
            k += e;
        }
    }

    // ---- GEMM ----
    __shared__ float A_sT[16 * 132];   // [k][t_local]  (transposed, padded)
    __shared__ float B_sT[16 * 132];   // [k][g_local]

    int tid = threadIdx.x;
    int tx = tid & 15, ty = tid >> 4;
    int g0 = blockIdx.x * 128;
    int t0 = blockIdx.y * 128;

    u64 acc[8][4];
    #pragma unroll
    for (int i = 0; i < 8; i++)
        #pragma unroll
        for (int j = 0; j < 4; j++) acc[i][j] = 0ull;

    for (int k0 = 0; k0 < ED; k0 += 16) {
        __syncthreads();
        #pragma unroll
        for (int i = 0; i < 2; i++) {
            int ff  = tid + i * 256;
            int row = ff >> 2;
            int c4  = (ff & 3) * 4;
            float4 va = *(const float4*)&emb[(size_t)(t0 + row) * ED + k0 + c4];
            A_sT[(c4 + 0) * 132 + row] = va.x;
            A_sT[(c4 + 1) * 132 + row] = va.y;
            A_sT[(c4 + 2) * 132 + row] = va.z;
            A_sT[(c4 + 3) * 132 + row] = va.w;
            float4 vb = *(const float4*)&w_ih[(size_t)(g0 + row) * ED + k0 + c4];
            B_sT[(c4 + 0) * 132 + row] = vb.x;
            B_sT[(c4 + 1) * 132 + row] = vb.y;
            B_sT[(c4 + 2) * 132 + row] = vb.z;
            B_sT[(c4 + 3) * 132 + row] = vb.w;
        }
        __syncthreads();
        #pragma unroll
        for (int k = 0; k < 16; k++) {
            float4 a0 = *(const float4*)&A_sT[k * 132 + ty * 4];
            float4 a1 = *(const float4*)&A_sT[k * 132 + 64 + ty * 4];
            u64 b0x = *(const u64*)&B_sT[k * 132 + tx * 4];
            u64 b0y = *(const u64*)&B_sT[k * 132 + tx * 4 + 2];
            u64 b1x = *(const u64*)&B_sT[k * 132 + 64 + tx * 4];
            u64 b1y = *(const u64*)&B_sT[k * 132 + 64 + tx * 4 + 2];
            float af[8] = {a0.x, a0.y, a0.z, a0.w, a1.x, a1.y, a1.z, a1.w};
            #pragma unroll
            for (int i = 0; i < 8; i++) {
                u64 ap = bcast2(af[i]);
                acc[i][0] = ffma2(ap, b0x, acc[i][0]);
                acc[i][1] = ffma2(ap, b0y, acc[i][1]);
                acc[i][2] = ffma2(ap, b1x, acc[i][2]);
                acc[i][3] = ffma2(ap, b1y, acc[i][3]);
            }
        }
    }

    float4 bia0 = *(const float4*)&b_ih[g0 + tx * 4];
    float4 bia1 = *(const float4*)&b_ih[g0 + 64 + tx * 4];
    #pragma unroll
    for (int i = 0; i < 8; i++) {
        int trow = t0 + (i >> 2) * 64 + ty * 4 + (i & 3);
        float2 c0 = unpack2(acc[i][0]);
        float2 c1 = unpack2(acc[i][1]);
        float2 c2 = unpack2(acc[i][2]);
        float2 c3 = unpack2(acc[i][3]);
        float4 o0 = make_float4(c0.x + bia0.x, c0.y + bia0.y, c1.x + bia0.z, c1.y + bia0.w);
        float4 o1 = make_float4(c2.x + bia1.x, c2.y + bia1.y, c3.x + bia1.z, c3.y + bia1.w);
        *(float4*)&g_Gtab[(size_t)trow * G3 + g0 + tx * 4]      = o0;
        *(float4*)&g_Gtab[(size_t)trow * G3 + g0 + 64 + tx * 4] = o1;
    }
}

// ------------------- persistent GRU recurrence ------------------------------
// CTA(bg,rg): 16 batches x 16 h-dims.
// Phase 1: thread(jl,ks) holds W_hh[g][jG][ks*32..+32) in regs (rotated k
//   order -> conflict-free LDS), accumulates 6 independent chains per b-pair,
//   2 shfl-xor rounds, stores 4-wide partials to smem.
// Phase 2: thread(b,j) reduces 12 partials + gi -> gates -> h_new.
// gi for step s+1 is prefetched BEFORE the grid barrier (latency hidden).
__global__ void __launch_bounds__(256, 1) gru_kernel(
    const int*   __restrict__ tokens,
    const float* __restrict__ w_hh,
    const float* __restrict__ b_hh,
    float*       __restrict__ out)
{
    __shared__ float h_s[16][HD];        // 32KB
    __shared__ float psum[16][16][12];   // 12KB: [b][j][g*4+slot]

    int tid = threadIdx.x;
    int bg = blockIdx.x & 3, rg = blockIdx.x >> 2;

    // phase-1 role
    int jl = tid >> 4, ks = tid & 15;
    int jG1 = rg * 16 + jl;
    // phase-2 / prefetch role
    int bl2 = tid >> 4, j2 = tid & 15;
    int bG2 = bg * 16 + bl2;
    int jG2 = rg * 16 + j2;

    // one-time W_hh register load, rotated k order
    u64 wr[16], wz[16], wn[16];
    #pragma unroll
    for (int i = 0; i < 16; i++) {
        int col = ks * 32 + ((2 * i + 2 * ks) & 31);
        wr[i] = *(const u64*)&w_hh[(size_t)(0 * HD + jG1) * HD + col];
        wz[i] = *(const u64*)&w_hh[(size_t)(1 * HD + jG1) * HD + col];
        wn[i] = *(const u64*)&w_hh[(size_t)(2 * HD + jG1) * HD + col];
    }
    float bhr = b_hh[jG2], bhz = b_hh[HD + jG2], bhn = b_hh[2 * HD + jG2];

    // prefetch gi(0), dest(0)
    int tok0 = __ldg(&tokens[bG2 * SQ]);
    const float* gp0 = &g_Gtab[(size_t)tok0 * G3 + jG2];
    float pr = __ldcs(gp0), pz = __ldcs(gp0 + HD), pn = __ldcs(gp0 + 2 * HD);
    int pd = __ldg(&g_dest[bG2]);

    for (int s = 0; s < SQ; s++) {
        // ---- load h(s) (cross-CTA data: L1-bypass) ----
        const float* hsrc = &g_h[s & 1][bg * 16 * HD];
        float4 hv[8];
        #pragma unroll
        for (int i = 0; i < 8; i++) {
            int f = tid + i * 256;
            hv[i] = __ldcg((const float4*)&hsrc[(f >> 7) * HD + (f & 127) * 4]);
        }
        #pragma unroll
        for (int i = 0; i < 8; i++) {
            int f = tid + i * 256;
            *(float4*)&h_s[f >> 7][(f & 127) * 4] = hv[i];
        }
        __syncthreads();

        // ---- phase 1: split-K partials, 2 batches at a time (6 acc chains) ----
        #pragma unroll 2
        for (int p = 0; p < 8; p++) {
            int b0 = 2 * p, b1 = 2 * p + 1;
            u64 a0r = 0, a0z = 0, a0n = 0, a1r = 0, a1z = 0, a1n = 0;
            #pragma unroll
            for (int i = 0; i < 16; i++) {
                int col = ks * 32 + ((2 * i + 2 * ks) & 31);
                u64 h0 = *(const u64*)&h_s[b0][col];
                u64 h1 = *(const u64*)&h_s[b1][col];
                a0r = ffma2(wr[i], h0, a0r);
                a1r = ffma2(wr[i], h1, a1r);
                a0z = ffma2(wz[i], h0, a0z);
                a1z = ffma2(wz[i], h1, a1z);
                a0n = ffma2(wn[i], h0, a0n);
                a1n = ffma2(wn[i], h1, a1n);
            }
            float v0r = hsum2(a0r), v0z = hsum2(a0z), v0n = hsum2(a0n);
            float v1r = hsum2(a1r), v1z = hsum2(a1z), v1n = hsum2(a1n);
            #pragma unroll
            for (int m = 1; m <= 2; m <<= 1) {
                v0r += __shfl_xor_sync(0xffffffffu, v0r, m);
                v0z += __shfl_xor_sync(0xffffffffu, v0z, m);
                v0n += __shfl_xor_sync(0xffffffffu, v0n, m);
                v1r += __shfl_xor_sync(0xffffffffu, v1r, m);
                v1z += __shfl_xor_sync(0xffffffffu, v1z, m);
                v1n += __shfl_xor_sync(0xffffffffu, v1n, m);
            }
            if ((ks & 3) == 0) {
                int slot = ks >> 2;
                psum[b0][jl][slot]     = v0r;
                psum[b0][jl][4 + slot] = v0z;
                psum[b0][jl][8 + slot] = v0n;
                psum[b1][jl][slot]     = v1r;
                psum[b1][jl][4 + slot] = v1z;
                psum[b1][jl][8 + slot] = v1n;
            }
        }

        // ---- prefetch gi(s+1) / dest(s+1): latency hides under barrier ----
        float nr = 0.f, nz = 0.f, nn2 = 0.f;
        int nd = -1;
        if (s + 1 < SQ) {
            int tk = __ldg(&tokens[bG2 * SQ + s + 1]);
            const float* gq = &g_Gtab[(size_t)tk * G3 + jG2];
            nr  = __ldcs(gq);
            nz  = __ldcs(gq + HD);
            nn2 = __ldcs(gq + 2 * HD);
            nd  = __ldg(&g_dest[(s + 1) * BS + bG2]);
        }
        __syncthreads();

        // ---- phase 2: reduce partials, gates, store ----
        float2 r01 = *(const float2*)&psum[bl2][j2][0];
        float2 r23 = *(const float2*)&psum[bl2][j2][2];
        float2 z01 = *(const float2*)&psum[bl2][j2][4];
        float2 z23 = *(const float2*)&psum[bl2][j2][6];
        float2 n01 = *(const float2*)&psum[bl2][j2][8];
        float2 n23 = *(const float2*)&psum[bl2][j2][10];
        float rsum = (r01.x + r01.y) + (r23.x + r23.y);
        float zsum = (z01.x + z01.y) + (z23.x + z23.y);
        float nsum = (n01.x + n01.y) + (n23.x + n23.y);
        float hprev = h_s[bl2][jG2];

        float r  = 1.f / (1.f + __expf(-(pr + rsum + bhr)));
        float z  = 1.f / (1.f + __expf(-(pz + zsum + bhz)));
        float nx = pn + r * (nsum + bhn);
        float t2 = __expf(-2.f * nx);
        float n  = 2.f / (1.f + t2) - 1.f;             // tanh, inf-safe
        float hnew = fmaf(z, hprev - n, n);            // (1-z)*n + z*h

        g_h[(s + 1) & 1][bG2 * HD + jG2] = hnew;
        if (pd >= 0) out[((size_t)pd * BS + bG2) * HD + jG2] = hnew;
        pr = nr; pz = nz; pn = nn2; pd = nd;

        // ---- per-batch-group barrier (32 CTAs), skipped on last step ----
        if (s + 1 < SQ) {
            __syncthreads();
            if (tid == 0) {
                __threadfence();
                atomicAdd(&g_ctr[bg * 32], 1u);
                unsigned tgt = 32u * (unsigned)(s + 1);
                while (ld_acq(&g_ctr[bg * 32]) < tgt) { }
            }
            __syncthreads();
        }
    }
}

// ------------------- launch -------------------------------------------------
extern "C" void kernel_launch(void* const* d_in, const int* in_sizes, int n_in,
                              void* d_out, int out_size) {
    const int*   tokens = (const int*)d_in[0];
    const float* emb    = (const float*)d_in[1];
    const float* w_ih   = (const float*)d_in[2];
    const float* w_hh   = (const float*)d_in[3];
    const float* b_ih   = (const float*)d_in[4];
    const float* b_hh   = (const float*)d_in[5];
    float* out = (float*)d_out;

    gtab_kernel<<<dim3(G3 / 128, VB / 128), 256>>>(emb, w_ih, b_ih, tokens);
    gru_kernel<<<NCTA, 256>>>(tokens, w_hh, b_hh, out);
}